// round 2
// baseline (speedup 1.0000x reference)
#include <cuda_runtime.h>

// ---------------------------------------------------------------------------
// SchNet interaction block, sm_100a.
// Pipeline:
//   jptr/iptr  : CSR pointers from sorted seg_j / seg_i (deterministic segsum)
//   XF         = x @ Wi                                  (fp32 tiled GEMM)
//   WIJK       = ssp(ssp(dijk@W1+b1)@W2+b2)              (tf32 mma, fused 2-GEMM)
//   AGG[a]     = sum_{p: seg_i[p]=a} XF[idx_j[p]] * sum_{e: seg_j[e]=p} WIJK[e]
//   H          = ssp(AGG@Wo+bo)                          (fp32)
//   V          = H@Wd+bd ; Y = x + V                     (fp32, dual output)
// Output: [Y (nA*128) | V (nA*128)]
// ---------------------------------------------------------------------------

#define LOG2F_C 0.6931471805599453f

static __device__ __forceinline__ float sspf(float x) {
    // shifted softplus: max(x,0) + log1p(exp(-|x|)) - log2, fast-math variant
    return fmaxf(x, 0.f) + __logf(1.f + __expf(-fabsf(x))) - LOG2F_C;
}

static __device__ __forceinline__ float tf32r(float x) {
    unsigned u;
    asm("cvt.rna.tf32.f32 %0, %1;" : "=r"(u) : "f"(x));
    return __uint_as_float(u);
}

static __device__ __forceinline__ void mma_tf32(float c[4], const unsigned a[4],
                                                unsigned b0, unsigned b1) {
    asm volatile(
        "mma.sync.aligned.m16n8k8.row.col.f32.tf32.tf32.f32 "
        "{%0,%1,%2,%3},{%4,%5,%6,%7},{%8,%9},{%0,%1,%2,%3};\n"
        : "+f"(c[0]), "+f"(c[1]), "+f"(c[2]), "+f"(c[3])
        : "r"(a[0]), "r"(a[1]), "r"(a[2]), "r"(a[3]), "r"(b0), "r"(b1));
}

// ------------------------------- scratch -----------------------------------
constexpr int NAMAX = 20000;
constexpr int NEMAX = 640000;

__device__ float g_XF[NAMAX * 128];
__device__ float g_WIJK[NEMAX * 128];   // 327.7 MB
__device__ float g_AGG[NAMAX * 128];
__device__ float g_H[NAMAX * 128];
__device__ int   g_jptr[NEMAX + 1];
__device__ int   g_iptr[NAMAX + 1];

// --------------------------- CSR pointer build -----------------------------
// ptr[v] = first index e with seg[e] >= v ; ptr[nseg] = n. seg is sorted.
__global__ void build_ptr_kernel(const int* __restrict__ seg, int n, int nseg,
                                 int* __restrict__ ptr) {
    int e = blockIdx.x * blockDim.x + threadIdx.x;
    if (e > n) return;
    int cur  = (e == n) ? nseg : seg[e];
    int prev = (e == 0) ? -1   : seg[e - 1];
    for (int v = prev + 1; v <= cur; v++) ptr[v] = e;
}

// ------------------- tf32 fused filter network kernel ----------------------
// Block: 128 rows x 128 cols, K=128, two chained GEMMs + ssp.
// 8 warps (256 threads): each warp owns ONE m16 x n128 slab (16 n8-tiles),
// giving 2 warps/SMSP for latency hiding and 64-reg accumulators.
// Smem pitches: A=132 (a-frag conflict-free), W=136 (b-frag conflict-free).
constexpr int SMEM_FILTER = (128 * 132 + 2 * 128 * 136 + 256) * 4;  // 207872 B

__device__ __forceinline__ void mma_warp_stage(const float* __restrict__ As,
                                               const float* __restrict__ Ws,
                                               int warp, int tg, int tm,
                                               float (&c)[16][4]) {
#pragma unroll
    for (int nt = 0; nt < 16; nt++)
#pragma unroll
        for (int j = 0; j < 4; j++) c[nt][j] = 0.f;

#pragma unroll 4
    for (int k0 = 0; k0 < 128; k0 += 8) {
        unsigned a[4];
        const float* ap = As + (warp * 16 + tg) * 132 + k0 + tm;
        a[0] = __float_as_uint(ap[0]);
        a[1] = __float_as_uint(ap[8 * 132]);
        a[2] = __float_as_uint(ap[4]);
        a[3] = __float_as_uint(ap[8 * 132 + 4]);
#pragma unroll
        for (int nt = 0; nt < 16; nt++) {
            const float* bp = Ws + (k0 + tm) * 136 + nt * 8 + tg;
            unsigned b0 = __float_as_uint(bp[0]);
            unsigned b1 = __float_as_uint(bp[4 * 136]);
            mma_tf32(c[nt], a, b0, b1);
        }
    }
}

__global__ void __launch_bounds__(256, 1)
filter_kernel(const float* __restrict__ dijk,
              const float* __restrict__ W1, const float* __restrict__ b1,
              const float* __restrict__ W2, const float* __restrict__ b2,
              int M) {
    extern __shared__ float sm[];
    float* As  = sm;                    // [128][132]
    float* W1s = sm + 128 * 132;        // [128][136]
    float* W2s = W1s + 128 * 136;       // [128][136]
    float* b1s = W2s + 128 * 136;       // [128]
    float* b2s = b1s + 128;             // [128]

    const int tid  = threadIdx.x;
    const int warp = tid >> 5;
    const int lane = tid & 31;
    const int tg   = lane >> 2;   // 0..7
    const int tm   = lane & 3;    // 0..3
    const int row0 = blockIdx.x * 128;

    // weights -> smem (tf32)
    for (int i = tid; i < 128 * 32; i += 256) {
        int k = i >> 5, n4 = (i & 31) << 2;
        float4 w1 = __ldg(((const float4*)W1) + i);
        float4 w2 = __ldg(((const float4*)W2) + i);
        float* p1 = &W1s[k * 136 + n4];
        p1[0] = tf32r(w1.x); p1[1] = tf32r(w1.y); p1[2] = tf32r(w1.z); p1[3] = tf32r(w1.w);
        float* p2 = &W2s[k * 136 + n4];
        p2[0] = tf32r(w2.x); p2[1] = tf32r(w2.y); p2[2] = tf32r(w2.z); p2[3] = tf32r(w2.w);
    }
    if (tid < 128) { b1s[tid] = b1[tid]; b2s[tid] = b2[tid]; }

    // A tile -> smem (tf32)
    for (int i = tid; i < 128 * 32; i += 256) {
        int m = i >> 5, k4 = (i & 31) << 2;
        int r = row0 + m;
        float4 a = (r < M) ? __ldg(((const float4*)dijk) + (size_t)r * 32 + (i & 31))
                           : make_float4(0.f, 0.f, 0.f, 0.f);
        float* p = &As[m * 132 + k4];
        p[0] = tf32r(a.x); p[1] = tf32r(a.y); p[2] = tf32r(a.z); p[3] = tf32r(a.w);
    }
    __syncthreads();

    float c[16][4];

    // stage 1: H = tf32(ssp(A@W1 + b1)), stored back into As (own 16 rows only,
    // so no block-level sync is needed between the two GEMM stages)
    mma_warp_stage(As, W1s, warp, tg, tm, c);
    __syncwarp();
    {
        int r = warp * 16 + tg;
#pragma unroll
        for (int nt = 0; nt < 16; nt++) {
            int col = nt * 8 + tm * 2;
            float bb0 = b1s[col], bb1 = b1s[col + 1];
            *(float2*)&As[r * 132 + col] =
                make_float2(tf32r(sspf(c[nt][0] + bb0)), tf32r(sspf(c[nt][1] + bb1)));
            *(float2*)&As[(r + 8) * 132 + col] =
                make_float2(tf32r(sspf(c[nt][2] + bb0)), tf32r(sspf(c[nt][3] + bb1)));
        }
    }
    __syncwarp();

    // stage 2: WIJK = ssp(H@W2 + b2) -> global
    mma_warp_stage(As, W2s, warp, tg, tm, c);
    {
        int r = row0 + warp * 16 + tg;
#pragma unroll
        for (int nt = 0; nt < 16; nt++) {
            int col = nt * 8 + tm * 2;
            float bb0 = b2s[col], bb1 = b2s[col + 1];
            if (r < M)
                *(float2*)&g_WIJK[(size_t)r * 128 + col] =
                    make_float2(sspf(c[nt][0] + bb0), sspf(c[nt][1] + bb1));
            if (r + 8 < M)
                *(float2*)&g_WIJK[((size_t)r + 8) * 128 + col] =
                    make_float2(sspf(c[nt][2] + bb0), sspf(c[nt][3] + bb1));
        }
    }
}

// ----------------------- fp32 generic 128-col GEMM -------------------------
// C = act(A@W + b) [ACT=1 -> ssp]; DUAL=1: outB=V, outA=X+V (residual)
constexpr int SMEM_G = (128 * 132 + 64 * 132 + 128) * 4;  // 101888 B

template <int ACT, int DUAL>
__global__ void __launch_bounds__(256)
gemm128_kernel(const float* __restrict__ A, const float* __restrict__ W,
               const float* __restrict__ bias, const float* __restrict__ X,
               float* __restrict__ outA, float* __restrict__ outB, int M) {
    extern __shared__ float sm[];
    float* Ws = sm;                  // [128][132]
    float* As = sm + 128 * 132;      // [64][132]
    float* bs = As + 64 * 132;       // [128]

    const int tid  = threadIdx.x;
    const int row0 = blockIdx.x * 64;

    for (int i = tid; i < 128 * 32; i += 256) {
        float4 w = __ldg(((const float4*)W) + i);
        *(float4*)&Ws[(i >> 5) * 132 + ((i & 31) << 2)] = w;
    }
    for (int i = tid; i < 64 * 32; i += 256) {
        int m = i >> 5;
        int r = row0 + m;
        float4 a = (r < M) ? __ldg(((const float4*)A) + (size_t)r * 32 + (i & 31))
                           : make_float4(0.f, 0.f, 0.f, 0.f);
        *(float4*)&As[m * 132 + ((i & 31) << 2)] = a;
    }
    if (tid < 128) bs[tid] = bias ? bias[tid] : 0.f;
    __syncthreads();

    const int tx = tid & 15;   // cols tx*8 .. +7
    const int ty = tid >> 4;   // rows ty*4 .. +3
    float acc[4][8];
#pragma unroll
    for (int i = 0; i < 4; i++)
#pragma unroll
        for (int j = 0; j < 8; j++) acc[i][j] = 0.f;

#pragma unroll 4
    for (int k = 0; k < 128; k++) {
        float av[4];
#pragma unroll
        for (int i = 0; i < 4; i++) av[i] = As[(ty * 4 + i) * 132 + k];
        float4 w0 = *(float4*)&Ws[k * 132 + tx * 8];
        float4 w1 = *(float4*)&Ws[k * 132 + tx * 8 + 4];
        float wv[8] = {w0.x, w0.y, w0.z, w0.w, w1.x, w1.y, w1.z, w1.w};
#pragma unroll
        for (int i = 0; i < 4; i++)
#pragma unroll
            for (int j = 0; j < 8; j++) acc[i][j] = fmaf(av[i], wv[j], acc[i][j]);
    }

#pragma unroll
    for (int i = 0; i < 4; i++) {
        int r = row0 + ty * 4 + i;
        if (r >= M) continue;
#pragma unroll
        for (int h = 0; h < 2; h++) {
            int col = tx * 8 + h * 4;
            float4 v;
            v.x = acc[i][h * 4 + 0] + bs[col + 0];
            v.y = acc[i][h * 4 + 1] + bs[col + 1];
            v.z = acc[i][h * 4 + 2] + bs[col + 2];
            v.w = acc[i][h * 4 + 3] + bs[col + 3];
            if (ACT) { v.x = sspf(v.x); v.y = sspf(v.y); v.z = sspf(v.z); v.w = sspf(v.w); }
            if (DUAL) {
                if (outB) *(float4*)&outB[(size_t)r * 128 + col] = v;
                float4 xr = __ldg((const float4*)&X[(size_t)r * 128 + col]);
                v.x += xr.x; v.y += xr.y; v.z += xr.z; v.w += xr.w;
            }
            *(float4*)&outA[(size_t)r * 128 + col] = v;
        }
    }
}

// ------------------- per-atom deterministic aggregation --------------------
// AGG[a] = sum_{p in iptr[a]..} XF[idx_j[p]] * (sum_{e in jptr[p]..} WIJK[e])
__global__ void __launch_bounds__(128)
agg_kernel(const int* __restrict__ idx_j) {
    const int a = blockIdx.x;
    const int c = threadIdx.x;
    const int plo = g_iptr[a], phi = g_iptr[a + 1];
    float acc = 0.f;
    for (int p = plo; p < phi; p++) {
        int elo = g_jptr[p], ehi = g_jptr[p + 1];
        float w = 0.f;
        for (int e = elo; e < ehi; e++) w += g_WIJK[(size_t)e * 128 + c];
        acc = fmaf(g_XF[idx_j[p] * 128 + c], w, acc);
    }
    g_AGG[a * 128 + c] = acc;
}

// -------------------------------- launch -----------------------------------
extern "C" void kernel_launch(void* const* d_in, const int* in_sizes, int n_in,
                              void* d_out, int out_size) {
    const float* x    = (const float*)d_in[0];
    const float* dijk = (const float*)d_in[1];
    const int*   idxj = (const int*)d_in[2];
    const int*   segi = (const int*)d_in[3];
    const int*   segj = (const int*)d_in[4];
    const float* W1   = (const float*)d_in[5];
    const float* b1   = (const float*)d_in[6];
    const float* W2   = (const float*)d_in[7];
    const float* b2   = (const float*)d_in[8];
    const float* Wi   = (const float*)d_in[9];
    const float* Wo   = (const float*)d_in[10];
    const float* bo   = (const float*)d_in[11];
    const float* Wd   = (const float*)d_in[12];
    const float* bd   = (const float*)d_in[13];

    const int nA   = in_sizes[0] / 128;   // atoms
    const int nIJK = in_sizes[1] / 128;   // edges (dijk rows, seg_j len)
    const int nP   = in_sizes[2];         // pairs (idx_j / seg_i len)

    cudaFuncSetAttribute(filter_kernel,
                         cudaFuncAttributeMaxDynamicSharedMemorySize, SMEM_FILTER);
    cudaFuncSetAttribute(gemm128_kernel<0, 0>,
                         cudaFuncAttributeMaxDynamicSharedMemorySize, SMEM_G);
    cudaFuncSetAttribute(gemm128_kernel<1, 0>,
                         cudaFuncAttributeMaxDynamicSharedMemorySize, SMEM_G);
    cudaFuncSetAttribute(gemm128_kernel<0, 1>,
                         cudaFuncAttributeMaxDynamicSharedMemorySize, SMEM_G);

    float *pXF, *pAGG, *pH;
    int *pjp, *pip;
    cudaGetSymbolAddress((void**)&pXF, g_XF);
    cudaGetSymbolAddress((void**)&pAGG, g_AGG);
    cudaGetSymbolAddress((void**)&pH, g_H);
    cudaGetSymbolAddress((void**)&pjp, g_jptr);
    cudaGetSymbolAddress((void**)&pip, g_iptr);

    // CSR pointers (deterministic segment sums)
    build_ptr_kernel<<<(nIJK + 256) / 256, 256>>>(segj, nIJK, nP, pjp);
    build_ptr_kernel<<<(nP + 256) / 256, 256>>>(segi, nP, nA, pip);

    // XF = x @ Wi
    gemm128_kernel<0, 0><<<(nA + 63) / 64, 256, SMEM_G>>>(
        x, Wi, nullptr, nullptr, pXF, nullptr, nA);

    // WIJK = ssp(ssp(dijk@W1+b1)@W2+b2)
    filter_kernel<<<(nIJK + 127) / 128, 256, SMEM_FILTER>>>(
        dijk, W1, b1, W2, b2, nIJK);

    // AGG
    agg_kernel<<<nA, 128>>>(idxj);

    // H = ssp(AGG@Wo + bo)
    gemm128_kernel<1, 0><<<(nA + 63) / 64, 256, SMEM_G>>>(
        pAGG, Wo, bo, nullptr, pH, nullptr, nA);

    // V = H@Wd + bd ; Y = x + V ; out = [Y | V]
    float* outY = (float*)d_out;
    float* outV = (out_size >= 2 * nA * 128) ? outY + (size_t)nA * 128 : nullptr;
    gemm128_kernel<0, 1><<<(nA + 63) / 64, 256, SMEM_G>>>(
        pH, Wd, bd, x, outY, outV, nA);
}

// round 5
// speedup vs baseline: 1.1809x; 1.1809x over previous
#include <cuda_runtime.h>

// ---------------------------------------------------------------------------
// SchNet interaction block, sm_100a — fused design (resubmit; infra flake x2).
//   jmap[e] = idx_j[seg_j[e]], amap[e] = seg_i[seg_j[e]]  (amap sorted!)
//   XF  = x @ Wi                          (tf32 mma)
//   filter_fused (per 128-edge tile):
//       H    = ssp(dijk@W1+b1)            (tf32 mma, smem-resident)
//       WIJK = ssp(H@W2+b2)               (tf32 mma, smem-resident)
//       AGG[amap[e]] += XF[jmap[e]] * WIJK[e]   (segment scan + atomicAdd)
//   H2  = ssp(AGG@Wo+bo)                  (tf32 mma)
//   V   = H2@Wd+bd ; Y = x + V            (tf32 mma, dual out)
// Output: [Y | V]
// ---------------------------------------------------------------------------

#define LOG2F_C 0.6931471805599453f

static __device__ __forceinline__ float sspf(float x) {
    return fmaxf(x, 0.f) + __logf(1.f + __expf(-fabsf(x))) - LOG2F_C;
}

static __device__ __forceinline__ float tf32r(float x) {
    unsigned u;
    asm("cvt.rna.tf32.f32 %0, %1;" : "=r"(u) : "f"(x));
    return __uint_as_float(u);
}

static __device__ __forceinline__ void mma_tf32(float c[4], const unsigned a[4],
                                                unsigned b0, unsigned b1) {
    asm volatile(
        "mma.sync.aligned.m16n8k8.row.col.f32.tf32.tf32.f32 "
        "{%0,%1,%2,%3},{%4,%5,%6,%7},{%8,%9},{%0,%1,%2,%3};\n"
        : "+f"(c[0]), "+f"(c[1]), "+f"(c[2]), "+f"(c[3])
        : "r"(a[0]), "r"(a[1]), "r"(a[2]), "r"(a[3]), "r"(b0), "r"(b1));
}

#define CP_ASYNC16(dst_u32, src_ptr) \
    asm volatile("cp.async.ca.shared.global [%0], [%1], 16;\n" :: "r"(dst_u32), "l"(src_ptr))
#define CP_COMMIT()  asm volatile("cp.async.commit_group;\n" ::: "memory")
#define CP_WAIT0()   asm volatile("cp.async.wait_group 0;\n" ::: "memory")

// ------------------------------- scratch -----------------------------------
constexpr int NAMAX = 20000;
constexpr int NEMAX = 640000;

__device__ float g_XF[NAMAX * 128];
__device__ float g_AGG[NAMAX * 128];
__device__ float g_H[NAMAX * 128];
__device__ int   g_jmap[NEMAX];
__device__ int   g_amap[NEMAX];

// --------------------------- map build + zero ------------------------------
__global__ void build_map_kernel(const int* __restrict__ seg_j,
                                 const int* __restrict__ seg_i,
                                 const int* __restrict__ idx_j, int n) {
    int e = blockIdx.x * blockDim.x + threadIdx.x;
    if (e >= n) return;
    int p = seg_j[e];
    g_jmap[e] = idx_j[p];
    g_amap[e] = seg_i[p];
}

__global__ void zero_kernel(float* __restrict__ p, int n4) {
    int i = blockIdx.x * blockDim.x + threadIdx.x;
    if (i < n4) ((float4*)p)[i] = make_float4(0.f, 0.f, 0.f, 0.f);
}

// ------------------ warp-stage: m32n64 per warp, K=128 ---------------------
// 8 warps: wm = warp&3 (rows wm*32..+32), wn = warp>>2 (cols wn*64..+64).
// As pitch 132 (a-frags conflict-free), Ws pitch 136 (b-frags conflict-free).
__device__ __forceinline__ void mma_stage(const float* __restrict__ As,
                                          const float* __restrict__ Ws,
                                          int wm, int wn, int tg, int tm,
                                          float (&c)[2][8][4]) {
#pragma unroll
    for (int mt = 0; mt < 2; mt++)
#pragma unroll
        for (int nt = 0; nt < 8; nt++)
#pragma unroll
            for (int j = 0; j < 4; j++) c[mt][nt][j] = 0.f;

#pragma unroll 4
    for (int k0 = 0; k0 < 128; k0 += 8) {
        unsigned a[2][4];
#pragma unroll
        for (int mt = 0; mt < 2; mt++) {
            const float* ap = As + (wm * 32 + mt * 16 + tg) * 132 + k0 + tm;
            a[mt][0] = __float_as_uint(ap[0]);
            a[mt][1] = __float_as_uint(ap[8 * 132]);
            a[mt][2] = __float_as_uint(ap[4]);
            a[mt][3] = __float_as_uint(ap[8 * 132 + 4]);
        }
        unsigned b[8][2];
#pragma unroll
        for (int nt = 0; nt < 8; nt++) {
            const float* bp = Ws + (k0 + tm) * 136 + wn * 64 + nt * 8 + tg;
            b[nt][0] = __float_as_uint(bp[0]);
            b[nt][1] = __float_as_uint(bp[4 * 136]);
        }
#pragma unroll
        for (int nt = 0; nt < 8; nt++) {
            mma_tf32(c[0][nt], a[0], b[nt][0], b[nt][1]);
            mma_tf32(c[1][nt], a[1], b[nt][0], b[nt][1]);
        }
    }
}

// ---------------------- fused filter + aggregation -------------------------
// smem: As[128*132] | Ws[128*136] | XFs[128*132] | b1s[128] | b2s[128]
//       | jms[128] | ams[128]
constexpr int SMEM_F =
    (16896 + 17408 + 16896 + 256) * 4 + 2 * 128 * 4;  // 206848 B

__global__ void __launch_bounds__(256, 1)
filter_fused_kernel(const float* __restrict__ dijk,
                    const float* __restrict__ W1, const float* __restrict__ b1,
                    const float* __restrict__ W2, const float* __restrict__ b2,
                    const float* __restrict__ XF, float* __restrict__ AGG,
                    int M) {
    extern __shared__ float sm[];
    float* As  = sm;                  // [128][132]
    float* Ws  = As + 16896;          // [128][136]  (W1, then W2)
    float* XFs = Ws + 17408;          // [128][132]
    float* b1s = XFs + 16896;         // [128]
    float* b2s = b1s + 128;           // [128]
    int*   jms = (int*)(b2s + 128);   // [128]
    int*   ams = jms + 128;           // [128]

    const int tid  = threadIdx.x;
    const int warp = tid >> 5;
    const int lane = tid & 31;
    const int wm   = warp & 3;
    const int wn   = warp >> 2;
    const int tg   = lane >> 2;
    const int tm   = lane & 3;
    const int row0 = blockIdx.x * 128;
    const int nvalid = min(128, M - row0);

    // ---- phase 0: biases, maps, W1, A tile ----
    if (tid < 128) {
        b1s[tid] = b1[tid];
        b2s[tid] = b2[tid];
        int e = row0 + tid;
        jms[tid] = (tid < nvalid) ? g_jmap[e] : 0;
        ams[tid] = (tid < nvalid) ? g_amap[e] : -1;
    }
    for (int i = tid; i < 4096; i += 256) {
        float4 w = __ldg(((const float4*)W1) + i);
        float* p = &Ws[(i >> 5) * 136 + ((i & 31) << 2)];
        p[0] = tf32r(w.x); p[1] = tf32r(w.y); p[2] = tf32r(w.z); p[3] = tf32r(w.w);
    }
    for (int i = tid; i < 4096; i += 256) {
        int m = i >> 5;
        int r = row0 + m;
        float4 a = (r < M) ? __ldg(((const float4*)dijk) + (size_t)r * 32 + (i & 31))
                           : make_float4(0.f, 0.f, 0.f, 0.f);
        float* p = &As[m * 132 + ((i & 31) << 2)];
        p[0] = tf32r(a.x); p[1] = tf32r(a.y); p[2] = tf32r(a.z); p[3] = tf32r(a.w);
    }
    __syncthreads();

    // async prefetch of gathered XF rows into XFs (overlaps both MMA stages)
    {
        unsigned base = (unsigned)__cvta_generic_to_shared(XFs);
        for (int i = tid; i < 4096; i += 256) {
            int r = i >> 5, ch = i & 31;
            const float* src = XF + (size_t)jms[r] * 128 + ch * 4;
            CP_ASYNC16(base + (unsigned)((r * 132 + ch * 4) * 4), src);
        }
        CP_COMMIT();
    }

    float c[2][8][4];

    // ---- phase 1: H = tf32(ssp(A@W1+b1)) -> As ; W2 -> Ws ----
    mma_stage(As, Ws, wm, wn, tg, tm, c);
    __syncthreads();
#pragma unroll
    for (int mt = 0; mt < 2; mt++) {
        int r = wm * 32 + mt * 16 + tg;
#pragma unroll
        for (int nt = 0; nt < 8; nt++) {
            int col = wn * 64 + nt * 8 + tm * 2;
            float bb0 = b1s[col], bb1 = b1s[col + 1];
            *(float2*)&As[r * 132 + col] =
                make_float2(tf32r(sspf(c[mt][nt][0] + bb0)), tf32r(sspf(c[mt][nt][1] + bb1)));
            *(float2*)&As[(r + 8) * 132 + col] =
                make_float2(tf32r(sspf(c[mt][nt][2] + bb0)), tf32r(sspf(c[mt][nt][3] + bb1)));
        }
    }
    for (int i = tid; i < 4096; i += 256) {
        float4 w = __ldg(((const float4*)W2) + i);
        float* p = &Ws[(i >> 5) * 136 + ((i & 31) << 2)];
        p[0] = tf32r(w.x); p[1] = tf32r(w.y); p[2] = tf32r(w.z); p[3] = tf32r(w.w);
    }
    __syncthreads();

    // ---- phase 2: WIJK = ssp(H@W2+b2) -> As ----
    mma_stage(As, Ws, wm, wn, tg, tm, c);
    __syncthreads();
#pragma unroll
    for (int mt = 0; mt < 2; mt++) {
        int r = wm * 32 + mt * 16 + tg;
#pragma unroll
        for (int nt = 0; nt < 8; nt++) {
            int col = wn * 64 + nt * 8 + tm * 2;
            float bb0 = b2s[col], bb1 = b2s[col + 1];
            *(float2*)&As[r * 132 + col] =
                make_float2(sspf(c[mt][nt][0] + bb0), sspf(c[mt][nt][1] + bb1));
            *(float2*)&As[(r + 8) * 132 + col] =
                make_float2(sspf(c[mt][nt][2] + bb0), sspf(c[mt][nt][3] + bb1));
        }
    }
    CP_WAIT0();
    __syncthreads();

    // ---- phase 3: segment scan over sorted amap, atomicAdd per segment ----
    {
        const int c0   = tid & 127;
        const int rbeg = (tid >> 7) * 64;
        const int rend = min(rbeg + 64, nvalid);
        if (rbeg < rend) {
            float acc = 0.f;
            int cura = ams[rbeg];
            for (int r = rbeg; r < rend; r++) {
                int a = ams[r];
                if (a != cura) {
                    atomicAdd(&AGG[(size_t)cura * 128 + c0], acc);
                    acc = 0.f;
                    cura = a;
                }
                acc = fmaf(XFs[r * 132 + c0], As[r * 132 + c0], acc);
            }
            atomicAdd(&AGG[(size_t)cura * 128 + c0], acc);
        }
    }
}

// --------------------- tf32 mma GEMM for the tail --------------------------
// C = act(A@W + b); DUAL: outB=V, outA=X+V. Tile 128 rows.
constexpr int SMEM_G = (16896 + 17408 + 128) * 4;  // 137728 B

template <int ACT, int DUAL>
__global__ void __launch_bounds__(256, 1)
gemm_mma_kernel(const float* __restrict__ A, const float* __restrict__ W,
                const float* __restrict__ bias, const float* __restrict__ X,
                float* __restrict__ outA, float* __restrict__ outB, int M) {
    extern __shared__ float sm[];
    float* As = sm;            // [128][132]
    float* Ws = As + 16896;    // [128][136]
    float* bs = Ws + 17408;    // [128]

    const int tid  = threadIdx.x;
    const int warp = tid >> 5;
    const int lane = tid & 31;
    const int wm   = warp & 3;
    const int wn   = warp >> 2;
    const int tg   = lane >> 2;
    const int tm   = lane & 3;
    const int row0 = blockIdx.x * 128;

    if (tid < 128) bs[tid] = bias ? bias[tid] : 0.f;
    for (int i = tid; i < 4096; i += 256) {
        float4 w = __ldg(((const float4*)W) + i);
        float* p = &Ws[(i >> 5) * 136 + ((i & 31) << 2)];
        p[0] = tf32r(w.x); p[1] = tf32r(w.y); p[2] = tf32r(w.z); p[3] = tf32r(w.w);
    }
    for (int i = tid; i < 4096; i += 256) {
        int m = i >> 5;
        int r = row0 + m;
        float4 a = (r < M) ? __ldg(((const float4*)A) + (size_t)r * 32 + (i & 31))
                           : make_float4(0.f, 0.f, 0.f, 0.f);
        float* p = &As[m * 132 + ((i & 31) << 2)];
        p[0] = tf32r(a.x); p[1] = tf32r(a.y); p[2] = tf32r(a.z); p[3] = tf32r(a.w);
    }
    __syncthreads();

    float c[2][8][4];
    mma_stage(As, Ws, wm, wn, tg, tm, c);

#pragma unroll
    for (int mt = 0; mt < 2; mt++) {
#pragma unroll
        for (int h = 0; h < 2; h++) {  // h=0: rows +0, h=1: rows +8
            int r = row0 + wm * 32 + mt * 16 + tg + h * 8;
            if (r >= M) continue;
#pragma unroll
            for (int nt = 0; nt < 8; nt++) {
                int col = wn * 64 + nt * 8 + tm * 2;
                float v0 = c[mt][nt][h * 2 + 0] + bs[col];
                float v1 = c[mt][nt][h * 2 + 1] + bs[col + 1];
                if (ACT) { v0 = sspf(v0); v1 = sspf(v1); }
                if (DUAL) {
                    if (outB) *(float2*)&outB[(size_t)r * 128 + col] = make_float2(v0, v1);
                    float2 xr = *(const float2*)&X[(size_t)r * 128 + col];
                    v0 += xr.x; v1 += xr.y;
                }
                *(float2*)&outA[(size_t)r * 128 + col] = make_float2(v0, v1);
            }
        }
    }
}

// -------------------------------- launch -----------------------------------
extern "C" void kernel_launch(void* const* d_in, const int* in_sizes, int n_in,
                              void* d_out, int out_size) {
    const float* x    = (const float*)d_in[0];
    const float* dijk = (const float*)d_in[1];
    const int*   idxj = (const int*)d_in[2];
    const int*   segi = (const int*)d_in[3];
    const int*   segj = (const int*)d_in[4];
    const float* W1   = (const float*)d_in[5];
    const float* b1   = (const float*)d_in[6];
    const float* W2   = (const float*)d_in[7];
    const float* b2   = (const float*)d_in[8];
    const float* Wi   = (const float*)d_in[9];
    const float* Wo   = (const float*)d_in[10];
    const float* bo   = (const float*)d_in[11];
    const float* Wd   = (const float*)d_in[12];
    const float* bd   = (const float*)d_in[13];

    const int nA   = in_sizes[0] / 128;
    const int nIJK = in_sizes[1] / 128;

    cudaFuncSetAttribute(filter_fused_kernel,
                         cudaFuncAttributeMaxDynamicSharedMemorySize, SMEM_F);
    cudaFuncSetAttribute(gemm_mma_kernel<0, 0>,
                         cudaFuncAttributeMaxDynamicSharedMemorySize, SMEM_G);
    cudaFuncSetAttribute(gemm_mma_kernel<1, 0>,
                         cudaFuncAttributeMaxDynamicSharedMemorySize, SMEM_G);
    cudaFuncSetAttribute(gemm_mma_kernel<0, 1>,
                         cudaFuncAttributeMaxDynamicSharedMemorySize, SMEM_G);

    float *pXF, *pAGG, *pH;
    cudaGetSymbolAddress((void**)&pXF, g_XF);
    cudaGetSymbolAddress((void**)&pAGG, g_AGG);
    cudaGetSymbolAddress((void**)&pH, g_H);

    // edge->atom / edge->source maps, AGG zeroing
    build_map_kernel<<<(nIJK + 255) / 256, 256>>>(segj, segi, idxj, nIJK);
    zero_kernel<<<(nA * 32 + 255) / 256, 256>>>(pAGG, nA * 32);

    // XF = x @ Wi
    gemm_mma_kernel<0, 0><<<(nA + 127) / 128, 256, SMEM_G>>>(
        x, Wi, nullptr, nullptr, pXF, nullptr, nA);

    // fused filter + aggregation
    filter_fused_kernel<<<(nIJK + 127) / 128, 256, SMEM_F>>>(
        dijk, W1, b1, W2, b2, pXF, pAGG, nIJK);

    // H = ssp(AGG@Wo+bo)
    gemm_mma_kernel<1, 0><<<(nA + 127) / 128, 256, SMEM_G>>>(
        pAGG, Wo, bo, nullptr, pH, nullptr, nA);

    // V = H@Wd+bd ; Y = x+V
    float* outY = (float*)d_out;
    float* outV = (out_size >= 2 * nA * 128) ? outY + (size_t)nA * 128 : nullptr;
    gemm_mma_kernel<0, 1><<<(nA + 127) / 128, 256, SMEM_G>>>(
        pH, Wd, bd, x, outY, outV, nA);
}

// round 6
// speedup vs baseline: 1.6602x; 1.4059x over previous
#include <cuda_runtime.h>

// ---------------------------------------------------------------------------
// SchNet interaction block, sm_100a — round 5: 16-warp filter, overlapped
// weight/XF staging, smem-resident scan.
//   jmap[e] = idx_j[seg_j[e]], amap[e] = seg_i[seg_j[e]]  (amap sorted)
//   XF  = x @ Wi                          (tf32 mma)
//   filter_fused (per 128-edge tile):
//       H    = ssp(dijk@W1+b1)            (tf32 mma)    | W2 cp.async in bg
//       WIJK = ssp(H@W2+b2)               (tf32 mma)    | XF gather in bg
//       AGG[amap[e]] += XF[jmap[e]] * WIJK[e]   (smem scan + atomicAdd)
//   H2  = ssp(AGG@Wo+bo); V = H2@Wd+bd; Y = x+V
// Output: [Y | V]
// ---------------------------------------------------------------------------

#define LOG2F_C 0.6931471805599453f

static __device__ __forceinline__ float sspf(float x) {
    return fmaxf(x, 0.f) + __logf(1.f + __expf(-fabsf(x))) - LOG2F_C;
}

static __device__ __forceinline__ float tf32r(float x) {
    unsigned u;
    asm("cvt.rna.tf32.f32 %0, %1;" : "=r"(u) : "f"(x));
    return __uint_as_float(u);
}

static __device__ __forceinline__ void mma_tf32(float c[4], const unsigned a[4],
                                                unsigned b0, unsigned b1) {
    asm volatile(
        "mma.sync.aligned.m16n8k8.row.col.f32.tf32.tf32.f32 "
        "{%0,%1,%2,%3},{%4,%5,%6,%7},{%8,%9},{%0,%1,%2,%3};\n"
        : "+f"(c[0]), "+f"(c[1]), "+f"(c[2]), "+f"(c[3])
        : "r"(a[0]), "r"(a[1]), "r"(a[2]), "r"(a[3]), "r"(b0), "r"(b1));
}

#define CP_ASYNC16(dst_u32, src_ptr) \
    asm volatile("cp.async.ca.shared.global [%0], [%1], 16;\n" :: "r"(dst_u32), "l"(src_ptr))
#define CP_COMMIT()  asm volatile("cp.async.commit_group;\n" ::: "memory")
#define CP_WAIT0()   asm volatile("cp.async.wait_group 0;\n" ::: "memory")
#define CP_WAIT1()   asm volatile("cp.async.wait_group 1;\n" ::: "memory")

// ------------------------------- scratch -----------------------------------
constexpr int NAMAX = 20000;
constexpr int NEMAX = 640000;

__device__ float g_XF[NAMAX * 128];
__device__ float g_AGG[NAMAX * 128];
__device__ float g_H[NAMAX * 128];
__device__ int   g_jmap[NEMAX];
__device__ int   g_amap[NEMAX];

// --------------------------- map build + zero ------------------------------
__global__ void build_map_kernel(const int* __restrict__ seg_j,
                                 const int* __restrict__ seg_i,
                                 const int* __restrict__ idx_j, int n) {
    int e = blockIdx.x * blockDim.x + threadIdx.x;
    if (e >= n) return;
    int p = seg_j[e];
    g_jmap[e] = idx_j[p];
    g_amap[e] = seg_i[p];
}

__global__ void zero_kernel(float* __restrict__ p, int n4) {
    int i = blockIdx.x * blockDim.x + threadIdx.x;
    if (i < n4) ((float4*)p)[i] = make_float4(0.f, 0.f, 0.f, 0.f);
}

// --------------- warp stage: m32n32 per warp, 16 warps, K=128 --------------
// wm = warp&3 (rows wm*32..+32), wn = warp>>2 (cols wn*32..+32).
// As pitch 132 (a-frags conflict-free), Ws pitch 136 (b-frags conflict-free).
__device__ __forceinline__ void mma_stage32(const float* __restrict__ As,
                                            const float* __restrict__ Ws,
                                            int wm, int wn, int tg, int tm,
                                            float (&c)[2][4][4]) {
#pragma unroll
    for (int mt = 0; mt < 2; mt++)
#pragma unroll
        for (int nt = 0; nt < 4; nt++)
#pragma unroll
            for (int j = 0; j < 4; j++) c[mt][nt][j] = 0.f;

#pragma unroll 4
    for (int k0 = 0; k0 < 128; k0 += 8) {
        unsigned a[2][4];
#pragma unroll
        for (int mt = 0; mt < 2; mt++) {
            const float* ap = As + (wm * 32 + mt * 16 + tg) * 132 + k0 + tm;
            a[mt][0] = __float_as_uint(ap[0]);
            a[mt][1] = __float_as_uint(ap[8 * 132]);
            a[mt][2] = __float_as_uint(ap[4]);
            a[mt][3] = __float_as_uint(ap[8 * 132 + 4]);
        }
        unsigned b[4][2];
#pragma unroll
        for (int nt = 0; nt < 4; nt++) {
            const float* bp = Ws + (k0 + tm) * 136 + wn * 32 + nt * 8 + tg;
            b[nt][0] = __float_as_uint(bp[0]);
            b[nt][1] = __float_as_uint(bp[4 * 136]);
        }
#pragma unroll
        for (int nt = 0; nt < 4; nt++) {
            mma_tf32(c[0][nt], a[0], b[nt][0], b[nt][1]);
            mma_tf32(c[1][nt], a[1], b[nt][0], b[nt][1]);
        }
    }
}

// ---------------------- fused filter + aggregation -------------------------
// smem floats: As[16896] Ws1[17408] Ws2[17408] b1s[128] b2s[128] + jms/ams ints
constexpr int SMEM_F = (16896 + 17408 + 17408 + 256) * 4 + 2 * 128 * 4; // 208896 B

__global__ void __launch_bounds__(512, 1)
filter_fused_kernel(const float* __restrict__ dijk,
                    const float* __restrict__ W1, const float* __restrict__ b1,
                    const float* __restrict__ W2, const float* __restrict__ b2,
                    const float* __restrict__ XF, float* __restrict__ AGG,
                    int M) {
    extern __shared__ float sm[];
    float* As  = sm;                  // [128][132]
    float* Ws1 = As + 16896;          // [128][136]  W1; later XF gather (pitch 136)
    float* Ws2 = Ws1 + 17408;         // [128][136]  W2 (cp.async, rounded in place)
    float* b1s = Ws2 + 17408;         // [128]
    float* b2s = b1s + 128;           // [128]
    int*   jms = (int*)(b2s + 128);   // [128]
    int*   ams = jms + 128;           // [128]

    const int tid  = threadIdx.x;
    const int warp = tid >> 5;
    const int lane = tid & 31;
    const int wm   = warp & 3;
    const int wn   = warp >> 2;       // 0..3
    const int tg   = lane >> 2;
    const int tm   = lane & 3;
    const int row0 = blockIdx.x * 128;
    const int nvalid = min(128, M - row0);

    // ---- phase 0 ----
    if (tid < 128) {
        b1s[tid] = b1[tid];
        b2s[tid] = b2[tid];
        int e = row0 + tid;
        jms[tid] = (tid < nvalid) ? g_jmap[e] : 0;
        ams[tid] = (tid < nvalid) ? g_amap[e] : -1;
    }
    // W2 -> Ws2 raw via cp.async (group A), overlapped with everything below
    {
        unsigned base = (unsigned)__cvta_generic_to_shared(Ws2);
        for (int i = tid; i < 4096; i += 512) {
            int k = i >> 5, n4 = (i & 31) << 2;
            CP_ASYNC16(base + (unsigned)((k * 136 + n4) * 4), W2 + i * 4);
        }
        CP_COMMIT();
    }
    // W1 -> Ws1 (tf32)
    for (int i = tid; i < 4096; i += 512) {
        int k = i >> 5, n4 = (i & 31) << 2;
        float4 w = __ldg(((const float4*)W1) + i);
        float* p = &Ws1[k * 136 + n4];
        p[0] = tf32r(w.x); p[1] = tf32r(w.y); p[2] = tf32r(w.z); p[3] = tf32r(w.w);
    }
    // A tile -> As (tf32)
    for (int i = tid; i < 4096; i += 512) {
        int m = i >> 5;
        int r = row0 + m;
        float4 a = (r < M) ? __ldg(((const float4*)dijk) + (size_t)r * 32 + (i & 31))
                           : make_float4(0.f, 0.f, 0.f, 0.f);
        float* p = &As[m * 132 + ((i & 31) << 2)];
        p[0] = tf32r(a.x); p[1] = tf32r(a.y); p[2] = tf32r(a.z); p[3] = tf32r(a.w);
    }
    __syncthreads();

    float c[2][4][4];

    // ---- stage 1: H = tf32(ssp(A@W1+b1)) ----
    mma_stage32(As, Ws1, wm, wn, tg, tm, c);
    __syncthreads();   // all A reads done

    // epilogue 1 -> As ; launch XF gather into Ws1 (group B)
#pragma unroll
    for (int mt = 0; mt < 2; mt++) {
        int r = wm * 32 + mt * 16 + tg;
#pragma unroll
        for (int nt = 0; nt < 4; nt++) {
            int col = wn * 32 + nt * 8 + tm * 2;
            float bb0 = b1s[col], bb1 = b1s[col + 1];
            *(float2*)&As[r * 132 + col] =
                make_float2(tf32r(sspf(c[mt][nt][0] + bb0)), tf32r(sspf(c[mt][nt][1] + bb1)));
            *(float2*)&As[(r + 8) * 132 + col] =
                make_float2(tf32r(sspf(c[mt][nt][2] + bb0)), tf32r(sspf(c[mt][nt][3] + bb1)));
        }
    }
    {
        unsigned base = (unsigned)__cvta_generic_to_shared(Ws1);
        for (int i = tid; i < 4096; i += 512) {
            int r = i >> 5, ch = i & 31;
            const float* src = XF + (size_t)jms[r] * 128 + ch * 4;
            CP_ASYNC16(base + (unsigned)((r * 136 + ch * 4) * 4), src);
        }
        CP_COMMIT();
    }
    CP_WAIT1();        // group A (W2) done for this thread
    __syncthreads();   // H complete + everyone's W2 copies drained

    // round W2 to tf32 in place
    for (int i = tid; i < 4096; i += 512) {
        int k = i >> 5, n4 = (i & 31) << 2;
        float* p = &Ws2[k * 136 + n4];
        p[0] = tf32r(p[0]); p[1] = tf32r(p[1]); p[2] = tf32r(p[2]); p[3] = tf32r(p[3]);
    }
    __syncthreads();

    // ---- stage 2: WIJK = ssp(H@W2+b2) ----
    mma_stage32(As, Ws2, wm, wn, tg, tm, c);
    __syncthreads();   // all H reads done
#pragma unroll
    for (int mt = 0; mt < 2; mt++) {
        int r = wm * 32 + mt * 16 + tg;
#pragma unroll
        for (int nt = 0; nt < 4; nt++) {
            int col = wn * 32 + nt * 8 + tm * 2;
            float bb0 = b2s[col], bb1 = b2s[col + 1];
            *(float2*)&As[r * 132 + col] =
                make_float2(sspf(c[mt][nt][0] + bb0), sspf(c[mt][nt][1] + bb1));
            *(float2*)&As[(r + 8) * 132 + col] =
                make_float2(sspf(c[mt][nt][2] + bb0), sspf(c[mt][nt][3] + bb1));
        }
    }
    CP_WAIT0();        // XF gather done for this thread
    __syncthreads();   // WIJK complete + everyone's XF copies drained

    // ---- scan: 4 row-chunks x 128 cols, smem only, atomics per segment ----
    {
        const int c0   = tid & 127;
        const int rbeg = (tid >> 7) * 32;
        const int rend = min(rbeg + 32, nvalid);
        if (rbeg < rend) {
            float acc = 0.f;
            int cura = ams[rbeg];
            for (int r = rbeg; r < rend; r++) {
                int a = ams[r];
                if (a != cura) {
                    atomicAdd(&AGG[(size_t)cura * 128 + c0], acc);
                    acc = 0.f;
                    cura = a;
                }
                acc = fmaf(Ws1[r * 136 + c0], As[r * 132 + c0], acc);
            }
            atomicAdd(&AGG[(size_t)cura * 128 + c0], acc);
        }
    }
}

// --------------------- tf32 mma GEMM for the tail --------------------------
// C = act(A@W + b); DUAL: outB=V, outA=X+V. Tile 128 rows, 512 threads.
constexpr int SMEM_G = (16896 + 17408 + 128) * 4;  // 137728 B

template <int ACT, int DUAL>
__global__ void __launch_bounds__(512, 1)
gemm_mma_kernel(const float* __restrict__ A, const float* __restrict__ W,
                const float* __restrict__ bias, const float* __restrict__ X,
                float* __restrict__ outA, float* __restrict__ outB, int M) {
    extern __shared__ float sm[];
    float* As = sm;            // [128][132]
    float* Ws = As + 16896;    // [128][136]
    float* bs = Ws + 17408;    // [128]

    const int tid  = threadIdx.x;
    const int warp = tid >> 5;
    const int lane = tid & 31;
    const int wm   = warp & 3;
    const int wn   = warp >> 2;
    const int tg   = lane >> 2;
    const int tm   = lane & 3;
    const int row0 = blockIdx.x * 128;

    if (tid < 128) bs[tid] = bias ? bias[tid] : 0.f;
    for (int i = tid; i < 4096; i += 512) {
        float4 w = __ldg(((const float4*)W) + i);
        float* p = &Ws[(i >> 5) * 136 + ((i & 31) << 2)];
        p[0] = tf32r(w.x); p[1] = tf32r(w.y); p[2] = tf32r(w.z); p[3] = tf32r(w.w);
    }
    for (int i = tid; i < 4096; i += 512) {
        int m = i >> 5;
        int r = row0 + m;
        float4 a = (r < M) ? __ldg(((const float4*)A) + (size_t)r * 32 + (i & 31))
                           : make_float4(0.f, 0.f, 0.f, 0.f);
        float* p = &As[m * 132 + ((i & 31) << 2)];
        p[0] = tf32r(a.x); p[1] = tf32r(a.y); p[2] = tf32r(a.z); p[3] = tf32r(a.w);
    }
    __syncthreads();

    float c[2][4][4];
    mma_stage32(As, Ws, wm, wn, tg, tm, c);

#pragma unroll
    for (int mt = 0; mt < 2; mt++) {
#pragma unroll
        for (int h = 0; h < 2; h++) {
            int r = row0 + wm * 32 + mt * 16 + tg + h * 8;
            if (r >= M) continue;
#pragma unroll
            for (int nt = 0; nt < 4; nt++) {
                int col = wn * 32 + nt * 8 + tm * 2;
                float v0 = c[mt][nt][h * 2 + 0] + bs[col];
                float v1 = c[mt][nt][h * 2 + 1] + bs[col + 1];
                if (ACT) { v0 = sspf(v0); v1 = sspf(v1); }
                if (DUAL) {
                    if (outB) *(float2*)&outB[(size_t)r * 128 + col] = make_float2(v0, v1);
                    float2 xr = *(const float2*)&X[(size_t)r * 128 + col];
                    v0 += xr.x; v1 += xr.y;
                }
                *(float2*)&outA[(size_t)r * 128 + col] = make_float2(v0, v1);
            }
        }
    }
}

// -------------------------------- launch -----------------------------------
extern "C" void kernel_launch(void* const* d_in, const int* in_sizes, int n_in,
                              void* d_out, int out_size) {
    const float* x    = (const float*)d_in[0];
    const float* dijk = (const float*)d_in[1];
    const int*   idxj = (const int*)d_in[2];
    const int*   segi = (const int*)d_in[3];
    const int*   segj = (const int*)d_in[4];
    const float* W1   = (const float*)d_in[5];
    const float* b1   = (const float*)d_in[6];
    const float* W2   = (const float*)d_in[7];
    const float* b2   = (const float*)d_in[8];
    const float* Wi   = (const float*)d_in[9];
    const float* Wo   = (const float*)d_in[10];
    const float* bo   = (const float*)d_in[11];
    const float* Wd   = (const float*)d_in[12];
    const float* bd   = (const float*)d_in[13];

    const int nA   = in_sizes[0] / 128;
    const int nIJK = in_sizes[1] / 128;

    cudaFuncSetAttribute(filter_fused_kernel,
                         cudaFuncAttributeMaxDynamicSharedMemorySize, SMEM_F);
    cudaFuncSetAttribute(gemm_mma_kernel<0, 0>,
                         cudaFuncAttributeMaxDynamicSharedMemorySize, SMEM_G);
    cudaFuncSetAttribute(gemm_mma_kernel<1, 0>,
                         cudaFuncAttributeMaxDynamicSharedMemorySize, SMEM_G);
    cudaFuncSetAttribute(gemm_mma_kernel<0, 1>,
                         cudaFuncAttributeMaxDynamicSharedMemorySize, SMEM_G);

    float *pXF, *pAGG, *pH;
    cudaGetSymbolAddress((void**)&pXF, g_XF);
    cudaGetSymbolAddress((void**)&pAGG, g_AGG);
    cudaGetSymbolAddress((void**)&pH, g_H);

    build_map_kernel<<<(nIJK + 255) / 256, 256>>>(segj, segi, idxj, nIJK);
    zero_kernel<<<(nA * 32 + 255) / 256, 256>>>(pAGG, nA * 32);

    // XF = x @ Wi
    gemm_mma_kernel<0, 0><<<(nA + 127) / 128, 512, SMEM_G>>>(
        x, Wi, nullptr, nullptr, pXF, nullptr, nA);

    // fused filter + aggregation
    filter_fused_kernel<<<(nIJK + 127) / 128, 512, SMEM_F>>>(
        dijk, W1, b1, W2, b2, pXF, pAGG, nIJK);

    // H = ssp(AGG@Wo+bo)
    gemm_mma_kernel<1, 0><<<(nA + 127) / 128, 512, SMEM_G>>>(
        pAGG, Wo, bo, nullptr, pH, nullptr, nA);

    // V = H@Wd+bd ; Y = x+V
    float* outY = (float*)d_out;
    float* outV = (out_size >= 2 * nA * 128) ? outY + (size_t)nA * 128 : nullptr;
    gemm_mma_kernel<0, 1><<<(nA + 127) / 128, 512, SMEM_G>>>(
        pH, Wd, bd, x, outY, outV, nA);
}